// round 11
// baseline (speedup 1.0000x reference)
#include <cuda_runtime.h>
#include <cuda_bf16.h>
#include <cstdint>

// ============================================================================
// S4D: K[i] = C @ A^i @ B, A diagonal.
//   K[i][m][d] = sum_n C[m][n] * a_n^i * B[n][d]
//   => GEMM: K[4096, 16384] = V[4096, 64] @ W[64, 16384]
// sm_103 generic target -> mma.sync bf16 (HMMA), bf16x3 split
// (hi*hi + hi*lo + lo*hi), operands pre-stored in fragment order (no SMEM).
// R11: occupancy experiment — warp tile 32x32, CTA 128x64, occ 3 (24 warps/SM,
// +50% latency hiding); B hi/lo interleaved (LDG.128). Prep: fp64 squaring
// table built block-locally in SMEM, r+8 factor trick, 2 prep launches.
// ============================================================================

#define L_LEN 4096
#define NS 64
#define DM 128
#define COLS_TOTAL (DM * DM)   // 16384

// A-fragment array: [blkf(256)][ks(4)][lane(32)] uint4 (a0..a3)
//   r0 = blkf*16 + lane/4, r1 = r0+8; n = ks*16 + (lane%4)*2 (+1,+8,+9)
#define VF_ELEMS (256 * 4 * 32)          // 32768
// B-fragment array (hi/lo interleaved): [nbf(2048)][ks(4)][lane(32)] uint4
//   .x .y = bhi(b0,b1) ; .z .w = blo(b0,b1) ; col = nbf*8 + lane/4
#define WF_ELEMS (2048 * 4 * 32)         // 262144

__device__ uint4 g_VFhi[VF_ELEMS];
__device__ uint4 g_VFlo[VF_ELEMS];
__device__ uint4 g_WF[WF_ELEMS];

__device__ __forceinline__ void mma_16816(float* c, const uint32_t* a,
                                          const uint32_t* b) {
    asm volatile(
        "mma.sync.aligned.m16n8k16.row.col.f32.bf16.bf16.f32 "
        "{%0,%1,%2,%3}, {%4,%5,%6,%7}, {%8,%9}, {%0,%1,%2,%3};"
        : "+f"(c[0]), "+f"(c[1]), "+f"(c[2]), "+f"(c[3])
        : "r"(a[0]), "r"(a[1]), "r"(a[2]), "r"(a[3]), "r"(b[0]), "r"(b[1]));
}

__device__ __forceinline__ uint32_t pack_bf2(__nv_bfloat16 x, __nv_bfloat16 y) {
    __nv_bfloat162 t(x, y);
    return *(uint32_t*)&t;
}

__device__ __forceinline__ void split2(float v0, float v1,
                                       uint32_t& hi, uint32_t& lo) {
    __nv_bfloat16 h0 = __float2bfloat16(v0);
    __nv_bfloat16 h1 = __float2bfloat16(v1);
    float l0 = v0 - __bfloat162float(h0);
    float l1 = v1 - __bfloat162float(h1);
    hi = pack_bf2(h0, h1);
    lo = pack_bf2(__float2bfloat16(l0), __float2bfloat16(l1));
}

// ============================================================================
// Prep 1: V in A-fragment order. Per-block fp64 squaring table in SMEM
// (12 dependent DMULs), powers as exact bit-product; pow(r+8) = pow(r)*a^8.
// ============================================================================
__global__ void s4d_prep_vf(const float* __restrict__ A) {
    __shared__ double s_pw[12][NS];

    if (threadIdx.x < NS) {
        double p = (double)A[threadIdx.x * (NS + 1)];   // diagonal entry
        s_pw[0][threadIdx.x] = p;
#pragma unroll
        for (int j = 1; j < 12; j++) { p = p * p; s_pw[j][threadIdx.x] = p; }
    }
    __syncthreads();

    int idx = blockIdx.x * blockDim.x + threadIdx.x;
    if (idx >= VF_ELEMS) return;
    int lane = idx & 31;
    int ks   = (idx >> 5) & 3;
    int blkf = idx >> 7;
    int g  = lane >> 2;              // 0..7 -> bit 3 of r0 is always 0
    int tg = lane & 3;
    int r0 = blkf * 16 + g;
    int k0 = ks * 16 + tg * 2;

    double p0[4];
#pragma unroll
    for (int q = 0; q < 4; q++) {
        int n = k0 + ((q >> 1) << 3) + (q & 1);   // k0, k0+1, k0+8, k0+9
        double v = 1.0;
#pragma unroll
        for (int j = 0; j < 12; j++)
            if ((r0 >> j) & 1) v *= s_pw[j][n];
        p0[q] = v;
    }
    // r1 = r0 + 8: exactly one extra factor a^(2^3)
    double p1[4];
#pragma unroll
    for (int q = 0; q < 4; q++) {
        int n = k0 + ((q >> 1) << 3) + (q & 1);
        p1[q] = p0[q] * s_pw[3][n];
    }

    uint4 hi, lo;
    split2((float)p0[0], (float)p0[1], hi.x, lo.x);   // (r0, n0 n1)
    split2((float)p1[0], (float)p1[1], hi.y, lo.y);   // (r1, n0 n1)
    split2((float)p0[2], (float)p0[3], hi.z, lo.z);   // (r0, n8 n9)
    split2((float)p1[2], (float)p1[3], hi.w, lo.w);   // (r1, n8 n9)
    g_VFhi[idx] = hi;
    g_VFlo[idx] = lo;
}

// ============================================================================
// Prep 2: W in B-fragment order, hi/lo interleaved in one uint4.
// ============================================================================
__global__ void s4d_prep_wf(const float* __restrict__ C, const float* __restrict__ Bm) {
    int idx = blockIdx.x * blockDim.x + threadIdx.x;
    if (idx >= WF_ELEMS) return;
    int lane = idx & 31;
    int ks   = (idx >> 5) & 3;
    int nbf  = idx >> 7;
    int g  = lane >> 2;
    int tg = lane & 3;
    int col = nbf * 8 + g;
    int k0  = ks * 16 + tg * 2;
    int m = col >> 7;
    int d = col & 127;

    const float* Crow = C + m * NS;
    float w0 = Crow[k0]     * Bm[k0 * DM + d];
    float w1 = Crow[k0 + 1] * Bm[(k0 + 1) * DM + d];
    float w8 = Crow[k0 + 8] * Bm[(k0 + 8) * DM + d];
    float w9 = Crow[k0 + 9] * Bm[(k0 + 9) * DM + d];

    uint4 w;                          // .xy = hi(b0,b1), .zw = lo(b0,b1)
    split2(w0, w1, w.x, w.z);
    split2(w8, w9, w.y, w.w);
    g_WF[idx] = w;
}

// ============================================================================
// Main: CTA = 128(i) x 64(col), 8 warps of 32x32 (4 m-strips x 2 n-strips).
// ~84 regs -> occupancy 3 (24 warps/SM). Direct LDG fragments, no SMEM.
// Per k-step: Ahi*(Bhi,Blo) then Alo*Bhi.
// ============================================================================
__global__ void __launch_bounds__(256, 3) s4d_mma_kernel(float* __restrict__ out) {
    const int tid  = threadIdx.x;
    const int wid  = tid >> 5;
    const int lane = tid & 31;
    const int m_w = (wid & 3) * 32;          // 0,32,64,96
    const int n_w = (wid >> 2) * 32;         // 0,32

    // A: ((by*8 + m_w/16 + mi)*4 + ks)*32 + lane   (mi 0..1)
    const int abase = (blockIdx.y * 8 + (m_w >> 4)) * 128 + lane;
    // B: ((bx*8 + n_w/8 + ni)*4 + ks)*32 + lane    (ni 0..3)
    const int bbase = (blockIdx.x * 8 + (n_w >> 3)) * 128 + lane;

    float c[2][4][4];
#pragma unroll
    for (int mi = 0; mi < 2; mi++)
#pragma unroll
        for (int ni = 0; ni < 4; ni++)
#pragma unroll
            for (int k = 0; k < 4; k++) c[mi][ni][k] = 0.0f;

#pragma unroll
    for (int ks = 0; ks < 4; ks++) {
        uint4 ahi[2];
        uint4 bw[4];
#pragma unroll
        for (int mi = 0; mi < 2; mi++) ahi[mi] = g_VFhi[abase + mi * 128 + ks * 32];
#pragma unroll
        for (int ni = 0; ni < 4; ni++) bw[ni] = g_WF[bbase + ni * 128 + ks * 32];

#pragma unroll
        for (int mi = 0; mi < 2; mi++)
#pragma unroll
            for (int ni = 0; ni < 4; ni++)
                mma_16816(c[mi][ni], (const uint32_t*)&ahi[mi],
                          (const uint32_t*)&bw[ni].x);     // B hi
#pragma unroll
        for (int mi = 0; mi < 2; mi++)
#pragma unroll
            for (int ni = 0; ni < 4; ni++)
                mma_16816(c[mi][ni], (const uint32_t*)&ahi[mi],
                          (const uint32_t*)&bw[ni].z);     // B lo

        uint4 alo[2];
#pragma unroll
        for (int mi = 0; mi < 2; mi++) alo[mi] = g_VFlo[abase + mi * 128 + ks * 32];
#pragma unroll
        for (int mi = 0; mi < 2; mi++)
#pragma unroll
            for (int ni = 0; ni < 4; ni++)
                mma_16816(c[mi][ni], (const uint32_t*)&alo[mi],
                          (const uint32_t*)&bw[ni].x);     // B hi
    }

    // ---- epilogue: fragment-direct float2 stores (full 32B sectors) ----
    const int gm = blockIdx.y * 128 + m_w + (lane >> 2);
    const int gn = blockIdx.x * 64 + n_w + (lane & 3) * 2;
#pragma unroll
    for (int mi = 0; mi < 2; mi++) {
        size_t r0 = (size_t)(gm + mi * 16) * COLS_TOTAL + gn;
        size_t r1 = r0 + (size_t)8 * COLS_TOTAL;
#pragma unroll
        for (int ni = 0; ni < 4; ni++) {
            *(float2*)(out + r0 + ni * 8) = make_float2(c[mi][ni][0], c[mi][ni][1]);
            *(float2*)(out + r1 + ni * 8) = make_float2(c[mi][ni][2], c[mi][ni][3]);
        }
    }
}

// ============================================================================
// launch
// ============================================================================
extern "C" void kernel_launch(void* const* d_in, const int* in_sizes, int n_in,
                              void* d_out, int out_size) {
    const float* A  = (const float*)d_in[0];   // (64, 64) diagonal
    const float* Bm = (const float*)d_in[1];   // (64, 128)
    const float* C  = (const float*)d_in[2];   // (128, 64)
    float* out = (float*)d_out;                // (4096, 128, 128) fp32

    s4d_prep_vf<<<VF_ELEMS / 256, 256>>>(A);
    s4d_prep_wf<<<WF_ELEMS / 256, 256>>>(C, Bm);

    dim3 grid(COLS_TOTAL / 64, L_LEN / 128);   // (256, 32) = 8192 CTAs
    s4d_mma_kernel<<<grid, 256>>>(out);
}

// round 13
// speedup vs baseline: 1.0449x; 1.0449x over previous
#include <cuda_runtime.h>
#include <cuda_bf16.h>
#include <cstdint>

// ============================================================================
// S4D: K[i] = C @ A^i @ B, A diagonal.
//   K[i][m][d] = sum_n C[m][n] * a_n^i * B[n][d]
//   => GEMM: K[4096, 16384] = V[4096, 64] @ W[64, 16384]
// sm_103 generic target -> mma.sync bf16 (HMMA), bf16x3 split
// (hi*hi + hi*lo + lo*hi), operands pre-stored in fragment order (no SMEM).
// R12: 2 launches total. Merged prep (V via block-local fp64 squaring table,
// W hi/lo interleaved uint4); main = proven R4 tiling (76.9us).
// ============================================================================

#define L_LEN 4096
#define NS 64
#define DM 128
#define COLS_TOTAL (DM * DM)   // 16384

// A-fragment array: [blkf(256)][ks(4)][lane(32)] uint4 (a0..a3)
//   r0 = blkf*16 + lane/4, r1 = r0+8; n = ks*16 + (lane%4)*2 (+1,+8,+9)
#define VF_ELEMS (256 * 4 * 32)          // 32768
// B-fragment array (hi/lo interleaved): [nbf(2048)][ks(4)][lane(32)] uint4
//   .x .y = bhi(b0,b1) ; .z .w = blo(b0,b1) ; col = nbf*8 + lane/4
#define WF_ELEMS (2048 * 4 * 32)         // 262144

__device__ uint4 g_VFhi[VF_ELEMS];
__device__ uint4 g_VFlo[VF_ELEMS];
__device__ uint4 g_WF[WF_ELEMS];

__device__ __forceinline__ void mma_16816(float* c, const uint32_t* a,
                                          const uint32_t* b) {
    asm volatile(
        "mma.sync.aligned.m16n8k16.row.col.f32.bf16.bf16.f32 "
        "{%0,%1,%2,%3}, {%4,%5,%6,%7}, {%8,%9}, {%0,%1,%2,%3};"
        : "+f"(c[0]), "+f"(c[1]), "+f"(c[2]), "+f"(c[3])
        : "r"(a[0]), "r"(a[1]), "r"(a[2]), "r"(a[3]), "r"(b[0]), "r"(b[1]));
}

__device__ __forceinline__ uint32_t pack_bf2(__nv_bfloat16 x, __nv_bfloat16 y) {
    __nv_bfloat162 t(x, y);
    return *(uint32_t*)&t;
}

__device__ __forceinline__ void split2(float v0, float v1,
                                       uint32_t& hi, uint32_t& lo) {
    __nv_bfloat16 h0 = __float2bfloat16(v0);
    __nv_bfloat16 h1 = __float2bfloat16(v1);
    float l0 = v0 - __bfloat162float(h0);
    float l1 = v1 - __bfloat162float(h1);
    hi = pack_bf2(h0, h1);
    lo = pack_bf2(__float2bfloat16(l0), __float2bfloat16(l1));
}

// ============================================================================
// Merged prep, ONE launch:
//   blocks [0, 128):    V fragments — block-local fp64 squaring table in SMEM,
//                       powers as exact bit-products, pow(r+8) = pow(r)*a^8.
//   blocks [128, 1152): W fragments — hi/lo interleaved in one uint4.
// ============================================================================
#define VF_BLOCKS (VF_ELEMS / 256)       // 128
#define WF_BLOCKS (WF_ELEMS / 256)       // 1024

__global__ void s4d_prep_frag(const float* __restrict__ A,
                              const float* __restrict__ C,
                              const float* __restrict__ Bm) {
    if (blockIdx.x < VF_BLOCKS) {
        __shared__ double s_pw[12][NS];
        if (threadIdx.x < NS) {
            double p = (double)A[threadIdx.x * (NS + 1)];   // diagonal entry
            s_pw[0][threadIdx.x] = p;
#pragma unroll
            for (int j = 1; j < 12; j++) { p = p * p; s_pw[j][threadIdx.x] = p; }
        }
        __syncthreads();

        int idx = blockIdx.x * 256 + threadIdx.x;
        int lane = idx & 31;
        int ks   = (idx >> 5) & 3;
        int blkf = idx >> 7;
        int g  = lane >> 2;              // 0..7 -> bit 3 of r0 is always 0
        int tg = lane & 3;
        int r0 = blkf * 16 + g;
        int k0 = ks * 16 + tg * 2;

        double p0[4], p1[4];
#pragma unroll
        for (int q = 0; q < 4; q++) {
            int n = k0 + ((q >> 1) << 3) + (q & 1);   // k0, k0+1, k0+8, k0+9
            double v = 1.0;
#pragma unroll
            for (int j = 0; j < 12; j++)
                if ((r0 >> j) & 1) v *= s_pw[j][n];
            p0[q] = v;
            p1[q] = v * s_pw[3][n];      // r1 = r0 + 8, bit 3 of r0 is clear
        }

        uint4 hi, lo;
        split2((float)p0[0], (float)p0[1], hi.x, lo.x);   // (r0, n0 n1)
        split2((float)p1[0], (float)p1[1], hi.y, lo.y);   // (r1, n0 n1)
        split2((float)p0[2], (float)p0[3], hi.z, lo.z);   // (r0, n8 n9)
        split2((float)p1[2], (float)p1[3], hi.w, lo.w);   // (r1, n8 n9)
        g_VFhi[idx] = hi;
        g_VFlo[idx] = lo;
    } else {
        int idx = (blockIdx.x - VF_BLOCKS) * 256 + threadIdx.x;
        int lane = idx & 31;
        int ks   = (idx >> 5) & 3;
        int nbf  = idx >> 7;
        int g  = lane >> 2;
        int tg = lane & 3;
        int col = nbf * 8 + g;
        int k0  = ks * 16 + tg * 2;
        int m = col >> 7;
        int d = col & 127;

        const float* Crow = C + m * NS;
        float w0 = Crow[k0]     * Bm[k0 * DM + d];
        float w1 = Crow[k0 + 1] * Bm[(k0 + 1) * DM + d];
        float w8 = Crow[k0 + 8] * Bm[(k0 + 8) * DM + d];
        float w9 = Crow[k0 + 9] * Bm[(k0 + 9) * DM + d];

        uint4 w;                          // .xy = hi(b0,b1), .zw = lo(b0,b1)
        split2(w0, w1, w.x, w.z);
        split2(w8, w9, w.y, w.w);
        g_WF[idx] = w;
    }
}

// ============================================================================
// Main (R4 shape, proven 76.9us): CTA = 128(i) x 128(col), 8 warps of 64x32.
// No SMEM. Fragments loaded directly (LDG.128) from fragment-order arrays.
// Per k-step: Ahi*(Bhi,Blo) then Alo*Bhi.
// ============================================================================
__global__ void __launch_bounds__(256, 2) s4d_mma_kernel(float* __restrict__ out) {
    const int tid  = threadIdx.x;
    const int wid  = tid >> 5;
    const int lane = tid & 31;
    const int m_w = (wid & 1) * 64;
    const int n_w = (wid >> 1) * 32;

    // fragment base indices (element granularity)
    const int abase = ((blockIdx.y * 8 + (m_w >> 4)) * 4) * 32 + lane;
    const int bbase = ((blockIdx.x * 16 + (n_w >> 3)) * 4) * 32 + lane;

    float c[4][4][4];
#pragma unroll
    for (int mi = 0; mi < 4; mi++)
#pragma unroll
        for (int ni = 0; ni < 4; ni++)
#pragma unroll
            for (int k = 0; k < 4; k++) c[mi][ni][k] = 0.0f;

#pragma unroll
    for (int ks = 0; ks < 4; ks++) {
        uint4 ahi[4];
        uint4 bw[4];
#pragma unroll
        for (int mi = 0; mi < 4; mi++) ahi[mi] = g_VFhi[abase + mi * 128 + ks * 32];
#pragma unroll
        for (int ni = 0; ni < 4; ni++) bw[ni] = g_WF[bbase + ni * 128 + ks * 32];

#pragma unroll
        for (int mi = 0; mi < 4; mi++)
#pragma unroll
            for (int ni = 0; ni < 4; ni++)
                mma_16816(c[mi][ni], (const uint32_t*)&ahi[mi],
                          (const uint32_t*)&bw[ni].x);     // B hi
#pragma unroll
        for (int mi = 0; mi < 4; mi++)
#pragma unroll
            for (int ni = 0; ni < 4; ni++)
                mma_16816(c[mi][ni], (const uint32_t*)&ahi[mi],
                          (const uint32_t*)&bw[ni].z);     // B lo

        uint4 alo[4];
#pragma unroll
        for (int mi = 0; mi < 4; mi++) alo[mi] = g_VFlo[abase + mi * 128 + ks * 32];
#pragma unroll
        for (int mi = 0; mi < 4; mi++)
#pragma unroll
            for (int ni = 0; ni < 4; ni++)
                mma_16816(c[mi][ni], (const uint32_t*)&alo[mi],
                          (const uint32_t*)&bw[ni].x);     // B hi
    }

    // ---- epilogue: fragment-direct float2 stores (full 32B sectors) ----
    const int gm = blockIdx.y * 128 + m_w + (lane >> 2);
    const int gn = blockIdx.x * 128 + n_w + (lane & 3) * 2;
#pragma unroll
    for (int mi = 0; mi < 4; mi++) {
        size_t r0 = (size_t)(gm + mi * 16) * COLS_TOTAL + gn;
        size_t r1 = r0 + (size_t)8 * COLS_TOTAL;
#pragma unroll
        for (int ni = 0; ni < 4; ni++) {
            *(float2*)(out + r0 + ni * 8) = make_float2(c[mi][ni][0], c[mi][ni][1]);
            *(float2*)(out + r1 + ni * 8) = make_float2(c[mi][ni][2], c[mi][ni][3]);
        }
    }
}

// ============================================================================
// launch: 2 launches total
// ============================================================================
extern "C" void kernel_launch(void* const* d_in, const int* in_sizes, int n_in,
                              void* d_out, int out_size) {
    const float* A  = (const float*)d_in[0];   // (64, 64) diagonal
    const float* Bm = (const float*)d_in[1];   // (64, 128)
    const float* C  = (const float*)d_in[2];   // (128, 64)
    float* out = (float*)d_out;                // (4096, 128, 128) fp32

    s4d_prep_frag<<<VF_BLOCKS + WF_BLOCKS, 256>>>(A, C, Bm);

    dim3 grid(COLS_TOTAL / 128, L_LEN / 128);  // (128, 32)
    s4d_mma_kernel<<<grid, 256>>>(out);
}

// round 14
// speedup vs baseline: 1.0529x; 1.0077x over previous
#include <cuda_runtime.h>
#include <cuda_bf16.h>
#include <cstdint>

// ============================================================================
// S4D: K[i] = C @ A^i @ B, A diagonal.
//   K[i][m][d] = sum_n C[m][n] * a_n^i * B[n][d]
//   => GEMM: K[4096, 16384] = V[4096, 64] @ W[64, 16384]
// sm_103 generic target -> mma.sync bf16 (HMMA), bf16x3 split
// (hi*hi + hi*lo + lo*hi), operands pre-stored in fragment order (no SMEM).
// R14: merged one-launch prep (proven ~7us) + EXACT R4 main kernel body
// (proven 76.9us: separate uint2 B hi/lo arrays -> short live ranges).
// ============================================================================

#define L_LEN 4096
#define NS 64
#define DM 128
#define COLS_TOTAL (DM * DM)   // 16384

// A-fragment array: [blkf(256)][ks(4)][lane(32)] uint4 (a0..a3)
//   r0 = blkf*16 + lane/4, r1 = r0+8; n = ks*16 + (lane%4)*2 (+1,+8,+9)
#define VF_ELEMS (256 * 4 * 32)          // 32768
// B-fragment arrays: [nbf(2048)][ks(4)][lane(32)] uint2 (b0, b1)
//   col = nbf*8 + lane/4; k = ks*16 + (lane%4)*2 (+1,+8,+9)
#define WF_ELEMS (2048 * 4 * 32)         // 262144

__device__ uint4 g_VFhi[VF_ELEMS];
__device__ uint4 g_VFlo[VF_ELEMS];
__device__ uint2 g_WFhi[WF_ELEMS];
__device__ uint2 g_WFlo[WF_ELEMS];

__device__ __forceinline__ void mma_16816(float* c, const uint32_t* a,
                                          const uint32_t* b) {
    asm volatile(
        "mma.sync.aligned.m16n8k16.row.col.f32.bf16.bf16.f32 "
        "{%0,%1,%2,%3}, {%4,%5,%6,%7}, {%8,%9}, {%0,%1,%2,%3};"
        : "+f"(c[0]), "+f"(c[1]), "+f"(c[2]), "+f"(c[3])
        : "r"(a[0]), "r"(a[1]), "r"(a[2]), "r"(a[3]), "r"(b[0]), "r"(b[1]));
}

__device__ __forceinline__ uint32_t pack_bf2(__nv_bfloat16 x, __nv_bfloat16 y) {
    __nv_bfloat162 t(x, y);
    return *(uint32_t*)&t;
}

__device__ __forceinline__ void split2(float v0, float v1,
                                       uint32_t& hi, uint32_t& lo) {
    __nv_bfloat16 h0 = __float2bfloat16(v0);
    __nv_bfloat16 h1 = __float2bfloat16(v1);
    float l0 = v0 - __bfloat162float(h0);
    float l1 = v1 - __bfloat162float(h1);
    hi = pack_bf2(h0, h1);
    lo = pack_bf2(__float2bfloat16(l0), __float2bfloat16(l1));
}

// ============================================================================
// Merged prep, ONE launch:
//   blocks [0, 128):    V fragments — block-local fp64 squaring table in SMEM,
//                       powers as exact bit-products, pow(r+8) = pow(r)*a^8.
//   blocks [128, 1152): W fragments — separate hi / lo uint2 stores.
// ============================================================================
#define VF_BLOCKS (VF_ELEMS / 256)       // 128
#define WF_BLOCKS (WF_ELEMS / 256)       // 1024

__global__ void s4d_prep_frag(const float* __restrict__ A,
                              const float* __restrict__ C,
                              const float* __restrict__ Bm) {
    if (blockIdx.x < VF_BLOCKS) {
        __shared__ double s_pw[12][NS];
        if (threadIdx.x < NS) {
            double p = (double)A[threadIdx.x * (NS + 1)];   // diagonal entry
            s_pw[0][threadIdx.x] = p;
#pragma unroll
            for (int j = 1; j < 12; j++) { p = p * p; s_pw[j][threadIdx.x] = p; }
        }
        __syncthreads();

        int idx = blockIdx.x * 256 + threadIdx.x;
        int lane = idx & 31;
        int ks   = (idx >> 5) & 3;
        int blkf = idx >> 7;
        int g  = lane >> 2;              // 0..7 -> bit 3 of r0 is always 0
        int tg = lane & 3;
        int r0 = blkf * 16 + g;
        int k0 = ks * 16 + tg * 2;

        double p0[4], p1[4];
#pragma unroll
        for (int q = 0; q < 4; q++) {
            int n = k0 + ((q >> 1) << 3) + (q & 1);   // k0, k0+1, k0+8, k0+9
            double v = 1.0;
#pragma unroll
            for (int j = 0; j < 12; j++)
                if ((r0 >> j) & 1) v *= s_pw[j][n];
            p0[q] = v;
            p1[q] = v * s_pw[3][n];      // r1 = r0 + 8, bit 3 of r0 is clear
        }

        uint4 hi, lo;
        split2((float)p0[0], (float)p0[1], hi.x, lo.x);   // (r0, n0 n1)
        split2((float)p1[0], (float)p1[1], hi.y, lo.y);   // (r1, n0 n1)
        split2((float)p0[2], (float)p0[3], hi.z, lo.z);   // (r0, n8 n9)
        split2((float)p1[2], (float)p1[3], hi.w, lo.w);   // (r1, n8 n9)
        g_VFhi[idx] = hi;
        g_VFlo[idx] = lo;
    } else {
        int idx = (blockIdx.x - VF_BLOCKS) * 256 + threadIdx.x;
        int lane = idx & 31;
        int ks   = (idx >> 5) & 3;
        int nbf  = idx >> 7;
        int g  = lane >> 2;
        int tg = lane & 3;
        int col = nbf * 8 + g;
        int k0  = ks * 16 + tg * 2;
        int m = col >> 7;
        int d = col & 127;

        const float* Crow = C + m * NS;
        float w0 = Crow[k0]     * Bm[k0 * DM + d];
        float w1 = Crow[k0 + 1] * Bm[(k0 + 1) * DM + d];
        float w8 = Crow[k0 + 8] * Bm[(k0 + 8) * DM + d];
        float w9 = Crow[k0 + 9] * Bm[(k0 + 9) * DM + d];

        uint2 hi, lo;
        split2(w0, w1, hi.x, lo.x);      // b0
        split2(w8, w9, hi.y, lo.y);      // b1
        g_WFhi[idx] = hi;
        g_WFlo[idx] = lo;
    }
}

// ============================================================================
// Main (EXACT R4 shape, proven 76.9us): CTA = 128(i) x 128(col), 8 warps of
// 64x32. No SMEM. Fragments loaded directly (LDG.128/LDG.64) from
// fragment-order arrays. Per k-step: Ahi*(Bhi,Blo) then Alo*Bhi.
// ============================================================================
__global__ void __launch_bounds__(256, 2) s4d_mma_kernel(float* __restrict__ out) {
    const int tid  = threadIdx.x;
    const int wid  = tid >> 5;
    const int lane = tid & 31;
    const int m_w = (wid & 1) * 64;
    const int n_w = (wid >> 1) * 32;

    // fragment base indices (element granularity)
    const int abase = ((blockIdx.y * 8 + (m_w >> 4)) * 4) * 32 + lane;
    const int bbase = ((blockIdx.x * 16 + (n_w >> 3)) * 4) * 32 + lane;

    float c[4][4][4];
#pragma unroll
    for (int mi = 0; mi < 4; mi++)
#pragma unroll
        for (int ni = 0; ni < 4; ni++)
#pragma unroll
            for (int k = 0; k < 4; k++) c[mi][ni][k] = 0.0f;

#pragma unroll
    for (int ks = 0; ks < 4; ks++) {
        uint4 ahi[4];
        uint2 bhi[4], blo[4];
#pragma unroll
        for (int mi = 0; mi < 4; mi++) ahi[mi] = g_VFhi[abase + mi * 128 + ks * 32];
#pragma unroll
        for (int ni = 0; ni < 4; ni++) bhi[ni] = g_WFhi[bbase + ni * 128 + ks * 32];
#pragma unroll
        for (int ni = 0; ni < 4; ni++) blo[ni] = g_WFlo[bbase + ni * 128 + ks * 32];

#pragma unroll
        for (int mi = 0; mi < 4; mi++)
#pragma unroll
            for (int ni = 0; ni < 4; ni++)
                mma_16816(c[mi][ni], (const uint32_t*)&ahi[mi],
                          (const uint32_t*)&bhi[ni]);
#pragma unroll
        for (int mi = 0; mi < 4; mi++)
#pragma unroll
            for (int ni = 0; ni < 4; ni++)
                mma_16816(c[mi][ni], (const uint32_t*)&ahi[mi],
                          (const uint32_t*)&blo[ni]);

        uint4 alo[4];
#pragma unroll
        for (int mi = 0; mi < 4; mi++) alo[mi] = g_VFlo[abase + mi * 128 + ks * 32];
#pragma unroll
        for (int mi = 0; mi < 4; mi++)
#pragma unroll
            for (int ni = 0; ni < 4; ni++)
                mma_16816(c[mi][ni], (const uint32_t*)&alo[mi],
                          (const uint32_t*)&bhi[ni]);
    }

    // ---- epilogue: fragment-direct float2 stores (full 32B sectors) ----
    const int gm = blockIdx.y * 128 + m_w + (lane >> 2);
    const int gn = blockIdx.x * 128 + n_w + (lane & 3) * 2;
#pragma unroll
    for (int mi = 0; mi < 4; mi++) {
        size_t r0 = (size_t)(gm + mi * 16) * COLS_TOTAL + gn;
        size_t r1 = r0 + (size_t)8 * COLS_TOTAL;
#pragma unroll
        for (int ni = 0; ni < 4; ni++) {
            *(float2*)(out + r0 + ni * 8) = make_float2(c[mi][ni][0], c[mi][ni][1]);
            *(float2*)(out + r1 + ni * 8) = make_float2(c[mi][ni][2], c[mi][ni][3]);
        }
    }
}

// ============================================================================
// launch: 2 launches total
// ============================================================================
extern "C" void kernel_launch(void* const* d_in, const int* in_sizes, int n_in,
                              void* d_out, int out_size) {
    const float* A  = (const float*)d_in[0];   // (64, 64) diagonal
    const float* Bm = (const float*)d_in[1];   // (64, 128)
    const float* C  = (const float*)d_in[2];   // (128, 64)
    float* out = (float*)d_out;                // (4096, 128, 128) fp32

    s4d_prep_frag<<<VF_BLOCKS + WF_BLOCKS, 256>>>(A, C, Bm);

    dim3 grid(COLS_TOTAL / 128, L_LEN / 128);  // (128, 32)
    s4d_mma_kernel<<<grid, 256>>>(out);
}